// round 2
// baseline (speedup 1.0000x reference)
#include <cuda_runtime.h>
#include <math.h>

#define NG 256
#define NB 8
#define NPTS (NB*NG*NG)
#define TSTEPS 8
#define INNERS 10

static __device__ __forceinline__ float sq(float x){ return x*x; }

// constants
#define DXF       0.024543692606170259f      // 2*pi/256
#define INVDX     40.743665431525205f        // 256/(2*pi)
#define INVDX2    (INVDX*INVDX)
#define VISCF     1e-3f
#define ONE256    (1.0f/256.0f)

// ---------------- scratch (no allocation allowed) ----------------
__device__ float  g_u [NPTS];
__device__ float  g_v [NPTS];
__device__ float  g_d0[NPTS];
__device__ float  g_d1[NPTS];
__device__ float  g_u1[NPTS];
__device__ float  g_v1[NPTS];
__device__ float  g_q [NPTS];
__device__ float2 g_G [NPTS];     // complex scratch for FFT pipeline
__device__ float2 g_tw[128];      // forward twiddles exp(-2*pi*i*k/256)
__device__ float  g_lam1[NG];     // FD laplacian 1D eigenvalues

// ---------------- tables ----------------
__global__ void k_tables(){
    int t = threadIdx.x;   // 256 threads
    if (t < 128){
        float s, c;
        sincospif(t*(1.0f/128.0f), &s, &c);   // angle = 2*pi*t/256
        g_tw[t] = make_float2(c, -s);
    }
    // lam1(k) = (2cos(2*pi*k/N)-2)/DX^2 = -4 sin^2(pi k / N)/DX^2  (no cancellation)
    float sn = sinpif(t*(1.0f/256.0f));
    g_lam1[t] = -4.0f*sn*sn*INVDX2;
}

// ---------------- init: de-interleave y0 ----------------
__global__ void k_init(const float* __restrict__ y0){
    int idx = blockIdx.x*256 + threadIdx.x;
    int b   = idx >> 16;
    int ij  = idx & 0xFFFF;
    const float* p = y0 + (size_t)b*(NG*NG*3) + (size_t)ij*3;
    g_u [idx] = p[0];
    g_v [idx] = p[1];
    g_d0[idx] = p[2];
}

// ---------------- van-Leer limited face flux ----------------
__device__ __forceinline__ float face_flux(float cm1, float c0, float c1, float c2,
                                           float uf, float dtdx){
    float dc     = c1 - c0;
    float f_low  = (uf >= 0.0f) ? uf*c0 : uf*c1;
    float f_high = uf*0.5f*(c0+c1) - 0.5f*uf*uf*dtdx*dc;
    float dc_up  = (uf >= 0.0f) ? (c0 - cm1) : (c2 - c1);
    float dc_safe = (fabsf(dc) > 1e-12f) ? dc : 1e-12f;
    // phi = r>0 ? 2r/(1+r) : 0 with r = dc_up/dc_safe  ==  2*dc_up/(dc_safe+dc_up)
    // valid when r>0 (same sign -> no cancellation in denominator)
    float phi = (dc_up * dc_safe > 0.0f) ? __fdividef(2.0f*dc_up, dc_safe + dc_up) : 0.0f;
    return f_low + phi*(f_high - f_low);
}

// ---------------- K1: advection + diffusion (explicit), density with old vel ----------------
__global__ void k_step(const float* __restrict__ dtp, int par){
    int idx  = blockIdx.x*256 + threadIdx.x;
    int j    = idx & 255;
    int i    = (idx >> 8) & 255;
    int base = idx & ~0xFFFF;

    const float dt   = __ldg(dtp);
    const float dtdx = dt * INVDX;

    const float* __restrict__ dfld = par ? g_d1 : g_d0;
    float*       __restrict__ dout = par ? g_d0 : g_d1;

    int im2 = ((i-2)&255)<<8, im1 = ((i-1)&255)<<8, i0 = i<<8,
        ip1 = ((i+1)&255)<<8, ip2 = ((i+2)&255)<<8;
    int jm2 = (j-2)&255, jm1 = (j-1)&255, jp1 = (j+1)&255, jp2 = (j+2)&255;

    // u stencil
    float u_im2 = __ldg(&g_u[base+im2+j]);
    float u_im1 = __ldg(&g_u[base+im1+j]);
    float u_c   = __ldg(&g_u[base+i0 +j]);
    float u_ip1 = __ldg(&g_u[base+ip1+j]);
    float u_ip2 = __ldg(&g_u[base+ip2+j]);
    float u_jm2 = __ldg(&g_u[base+i0+jm2]);
    float u_jm1 = __ldg(&g_u[base+i0+jm1]);
    float u_jp1 = __ldg(&g_u[base+i0+jp1]);
    float u_jp2 = __ldg(&g_u[base+i0+jp2]);
    // v stencil
    float v_im2 = __ldg(&g_v[base+im2+j]);
    float v_im1 = __ldg(&g_v[base+im1+j]);
    float v_c   = __ldg(&g_v[base+i0 +j]);
    float v_ip1 = __ldg(&g_v[base+ip1+j]);
    float v_ip2 = __ldg(&g_v[base+ip2+j]);
    float v_jm2 = __ldg(&g_v[base+i0+jm2]);
    float v_jm1 = __ldg(&g_v[base+i0+jm1]);
    float v_jp1 = __ldg(&g_v[base+i0+jp1]);
    float v_jp2 = __ldg(&g_v[base+i0+jp2]);
    // d stencil
    float d_im2 = __ldg(&dfld[base+im2+j]);
    float d_im1 = __ldg(&dfld[base+im1+j]);
    float d_c   = __ldg(&dfld[base+i0 +j]);
    float d_ip1 = __ldg(&dfld[base+ip1+j]);
    float d_ip2 = __ldg(&dfld[base+ip2+j]);
    float d_jm2 = __ldg(&dfld[base+i0+jm2]);
    float d_jm1 = __ldg(&dfld[base+i0+jm1]);
    float d_jp1 = __ldg(&dfld[base+i0+jp1]);
    float d_jp2 = __ldg(&dfld[base+i0+jp2]);

    // face velocities (shared by all advected fields)
    float uf_p = 0.5f*(u_c   + u_ip1);   // face i+1/2
    float uf_m = 0.5f*(u_im1 + u_c  );   // face i-1/2
    float vf_p = 0.5f*(v_c   + v_jp1);   // face j+1/2
    float vf_m = 0.5f*(v_jm1 + v_c  );   // face j-1/2

    // --- u tendency ---
    {
        float Fip = face_flux(u_im1, u_c,   u_ip1, u_ip2, uf_p, dtdx);
        float Fim = face_flux(u_im2, u_im1, u_c,   u_ip1, uf_m, dtdx);
        float Fjp = face_flux(u_jm1, u_c,   u_jp1, u_jp2, vf_p, dtdx);
        float Fjm = face_flux(u_jm2, u_jm1, u_c,   u_jp1, vf_m, dtdx);
        float tend = -((Fip - Fim) + (Fjp - Fjm)) * INVDX;
        float lap  = (u_im1 + u_ip1 + u_jm1 + u_jp1 - 4.0f*u_c) * INVDX2;
        g_u1[idx] = u_c + dt*(tend + VISCF*lap);
    }
    // --- v tendency ---
    {
        float Fip = face_flux(v_im1, v_c,   v_ip1, v_ip2, uf_p, dtdx);
        float Fim = face_flux(v_im2, v_im1, v_c,   v_ip1, uf_m, dtdx);
        float Fjp = face_flux(v_jm1, v_c,   v_jp1, v_jp2, vf_p, dtdx);
        float Fjm = face_flux(v_jm2, v_jm1, v_c,   v_jp1, vf_m, dtdx);
        float tend = -((Fip - Fim) + (Fjp - Fjm)) * INVDX;
        float lap  = (v_im1 + v_ip1 + v_jm1 + v_jp1 - 4.0f*v_c) * INVDX2;
        g_v1[idx] = v_c + dt*(tend + VISCF*lap);
    }
    // --- density tendency (old velocity, no diffusion) ---
    {
        float Fip = face_flux(d_im1, d_c,   d_ip1, d_ip2, uf_p, dtdx);
        float Fim = face_flux(d_im2, d_im1, d_c,   d_ip1, uf_m, dtdx);
        float Fjp = face_flux(d_jm1, d_c,   d_jp1, d_jp2, vf_p, dtdx);
        float Fjm = face_flux(d_jm2, d_jm1, d_c,   d_jp1, vf_m, dtdx);
        float tend = -((Fip - Fim) + (Fjp - Fjm)) * INVDX;
        dout[idx] = d_c + dt*tend;
    }
}

// ---------------- shared-memory Stockham 256-pt FFT (128 threads) ----------------
__device__ __forceinline__ void fft256(float2* sA, float2* sB, const float2* tw,
                                       int t, bool inv){
    float2* src = sA;
    float2* dst = sB;
    #pragma unroll
    for (int st = 0; st < 8; st++){
        int s = 1 << st;
        int p = t >> st;
        int q = t & (s - 1);
        float2 a  = src[t];
        float2 bb = src[t + 128];
        float2 w  = tw[p << st];
        float wy  = inv ? -w.y : w.y;
        float dr = a.x - bb.x;
        float di = a.y - bb.y;
        int   o  = q + (p << (st + 1));
        dst[o]     = make_float2(a.x + bb.x, a.y + bb.y);
        dst[o + s] = make_float2(dr*w.x - di*wy, dr*wy + di*w.x);
        __syncthreads();
        float2* tmp = src; src = dst; dst = tmp;
    }
    // result ends in sA (8 swaps)
}

// ---------------- K2: divergence + row FFT ----------------
__global__ void k_divfft(){
    __shared__ float2 sA[256];
    __shared__ float2 sB[256];
    __shared__ float2 stw[128];
    int t = threadIdx.x;                 // 128
    int i = blockIdx.x;
    int b = blockIdx.y;
    stw[t] = g_tw[t];
    int base = b << 16;
    int rowb = base + (i << 8);
    int rowm = base + (((i - 1) & 255) << 8);
    #pragma unroll
    for (int k = 0; k < 2; k++){
        int j = t + k*128;
        float du = g_u1[rowb + j] - g_u1[rowm + j];
        float dv = g_v1[rowb + j] - g_v1[rowb + ((j - 1) & 255)];
        sA[j] = make_float2((du + dv) * INVDX, 0.0f);
    }
    __syncthreads();
    fft256(sA, sB, stw, t, false);
    #pragma unroll
    for (int k = 0; k < 2; k++){
        int j = t + k*128;
        g_G[rowb + j] = sA[j];
    }
}

// ---------------- K3: column FFT * inv_lam * inverse column FFT ----------------
__global__ void k_colsolve(){
    __shared__ float2 sA[256];
    __shared__ float2 sB[256];
    __shared__ float2 stw[128];
    int t  = threadIdx.x;                // 128
    int k2 = blockIdx.x;
    int b  = blockIdx.y;
    stw[t] = g_tw[t];
    int base = (b << 16) + k2;
    sA[t]       = g_G[base + (t << 8)];
    sA[t + 128] = g_G[base + ((t + 128) << 8)];
    __syncthreads();
    fft256(sA, sB, stw, t, false);
    // scale by pseudo-inverse of FD laplacian eigenvalues
    float l2 = __ldg(&g_lam1[k2]);
    #pragma unroll
    for (int k = 0; k < 2; k++){
        int k1 = t + k*128;
        float l1 = __ldg(&g_lam1[k1]);
        float sc = (k1 == 0 && k2 == 0) ? 0.0f : __fdividef(1.0f, l1 + l2);
        sA[k1].x *= sc;
        sA[k1].y *= sc;
    }
    __syncthreads();
    fft256(sA, sB, stw, t, true);
    #pragma unroll
    for (int k = 0; k < 2; k++){
        int k1 = t + k*128;
        float2 vch = sA[k1];
        g_G[base + (k1 << 8)] = make_float2(vch.x * ONE256, vch.y * ONE256);
    }
}

// ---------------- K4: inverse row FFT -> q ----------------
__global__ void k_rowifft(){
    __shared__ float2 sA[256];
    __shared__ float2 sB[256];
    __shared__ float2 stw[128];
    int t = threadIdx.x;                 // 128
    int i = blockIdx.x;
    int b = blockIdx.y;
    stw[t] = g_tw[t];
    int rowb = (b << 16) + (i << 8);
    sA[t]       = g_G[rowb + t];
    sA[t + 128] = g_G[rowb + t + 128];
    __syncthreads();
    fft256(sA, sB, stw, t, true);
    g_q[rowb + t]       = sA[t].x       * ONE256;
    g_q[rowb + t + 128] = sA[t + 128].x * ONE256;
}

// ---------------- K5: projection correction (+ optional output write) ----------------
__global__ void k_correct(float* __restrict__ out, int par_new, int tstep, int wout){
    int idx  = blockIdx.x*256 + threadIdx.x;
    int j    = idx & 255;
    int i    = (idx >> 8) & 255;
    int base = idx & ~0xFFFF;
    int i0   = i << 8;
    int ip1  = ((i + 1) & 255) << 8;
    int jp1  = (j + 1) & 255;

    float qc  = g_q[idx];
    float qip = g_q[base + ip1 + j];
    float qjp = g_q[base + i0 + jp1];

    float un = g_u1[idx] - (qip - qc) * INVDX;
    float vn = g_v1[idx] - (qjp - qc) * INVDX;
    g_u[idx] = un;
    g_v[idx] = vn;

    if (wout){
        const float* __restrict__ dnew = par_new ? g_d1 : g_d0;
        float dd = dnew[idx];
        int b  = idx >> 16;
        int ij = idx & 0xFFFF;
        size_t o = ((size_t)b * TSTEPS + (size_t)tstep) * (size_t)(NG*NG*3) + (size_t)ij * 3;
        out[o + 0] = un;
        out[o + 1] = vn;
        out[o + 2] = dd;
    }
}

// ---------------- launch ----------------
extern "C" void kernel_launch(void* const* d_in, const int* in_sizes, int n_in,
                              void* d_out, int out_size){
    const float* y0  = (const float*)d_in[0];
    const float* dtp = (const float*)d_in[1];
    float* out = (float*)d_out;

    k_tables<<<1, 256>>>();
    k_init<<<NPTS/256, 256>>>(y0);

    int par = 0;   // which buffer currently holds density (0 -> g_d0)
    for (int t = 0; t < TSTEPS; t++){
        for (int k = 0; k < INNERS; k++){
            k_step<<<NPTS/256, 256>>>(dtp, par);
            k_divfft  <<<dim3(NG, NB), 128>>>();
            k_colsolve<<<dim3(NG, NB), 128>>>();
            k_rowifft <<<dim3(NG, NB), 128>>>();
            int par_new = par ^ 1;
            k_correct<<<NPTS/256, 256>>>(out, par_new, t, (k == INNERS-1) ? 1 : 0);
            par = par_new;
        }
    }
}

// round 4
// speedup vs baseline: 1.3941x; 1.3941x over previous
#include <cuda_runtime.h>
#include <math.h>

#define NG 256
#define NB 8
#define NPTS (NB*NG*NG)
#define TSTEPS 8
#define INNERS 10
#define K2P 132            // padded half-spectrum columns (0..128 used)

#define INVDX     40.743665431525205f        // 256/(2*pi)
#define INVDX2    (INVDX*INVDX)
#define VISCF     1e-3f
#define ONE65536  1.52587890625e-5f          // 1/65536

#define SPAD(i) ((i) + ((i)>>4))
#define FSZ 272

// ---------------- scratch (no allocation allowed) ----------------
__device__ float  g_u [NPTS];
__device__ float  g_v [NPTS];
__device__ float  g_d0[NPTS];
__device__ float  g_d1[NPTS];
__device__ float  g_u1[NPTS];
__device__ float  g_v1[NPTS];
__device__ float  g_q [NPTS];
__device__ float2 g_G [NB*NG*K2P];   // half-spectrum scratch, layout [b][i][k2]
__device__ float2 g_tw[64];          // exp(-2*pi*i*k/256), k<64
__device__ float  g_lam1[NG];        // FD laplacian 1D eigenvalues

// ---------------- tables ----------------
__global__ void k_tables(){
    int t = threadIdx.x;   // 256 threads
    if (t < 64){
        float s, c;
        sincospif(t*(1.0f/128.0f), &s, &c);   // angle = 2*pi*t/256
        g_tw[t] = make_float2(c, -s);
    }
    float sn = sinpif(t*(1.0f/256.0f));
    g_lam1[t] = -4.0f*sn*sn*INVDX2;           // = (2cos(2pi k/N)-2)/DX^2, cancellation-free
}

// ---------------- init: de-interleave y0 ----------------
__global__ void k_init(const float* __restrict__ y0){
    int idx = blockIdx.x*256 + threadIdx.x;
    int b   = idx >> 16;
    int ij  = idx & 0xFFFF;
    const float* p = y0 + (size_t)b*(NG*NG*3) + (size_t)ij*3;
    g_u [idx] = p[0];
    g_v [idx] = p[1];
    g_d0[idx] = p[2];
}

// ---------------- van-Leer limited face flux ----------------
__device__ __forceinline__ float face_flux(float cm1, float c0, float c1, float c2,
                                           float uf, float dtdx){
    float dc     = c1 - c0;
    float f_low  = (uf >= 0.0f) ? uf*c0 : uf*c1;
    float f_high = uf*0.5f*(c0+c1) - 0.5f*uf*uf*dtdx*dc;
    float dc_up  = (uf >= 0.0f) ? (c0 - cm1) : (c2 - c1);
    float dc_safe = (fabsf(dc) > 1e-12f) ? dc : 1e-12f;
    float phi = (dc_up * dc_safe > 0.0f) ? __fdividef(2.0f*dc_up, dc_safe + dc_up) : 0.0f;
    return f_low + phi*(f_high - f_low);
}

// ---------------- K1: advection + diffusion ----------------
__global__ void k_step(const float* __restrict__ dtp, int par){
    int idx  = blockIdx.x*256 + threadIdx.x;
    int j    = idx & 255;
    int i    = (idx >> 8) & 255;
    int base = idx & ~0xFFFF;

    const float dt   = __ldg(dtp);
    const float dtdx = dt * INVDX;

    const float* __restrict__ dfld = par ? g_d1 : g_d0;
    float*       __restrict__ dout = par ? g_d0 : g_d1;

    int im2 = ((i-2)&255)<<8, im1 = ((i-1)&255)<<8, i0 = i<<8,
        ip1 = ((i+1)&255)<<8, ip2 = ((i+2)&255)<<8;
    int jm2 = (j-2)&255, jm1 = (j-1)&255, jp1 = (j+1)&255, jp2 = (j+2)&255;

    float u_im2 = __ldg(&g_u[base+im2+j]);
    float u_im1 = __ldg(&g_u[base+im1+j]);
    float u_c   = __ldg(&g_u[base+i0 +j]);
    float u_ip1 = __ldg(&g_u[base+ip1+j]);
    float u_ip2 = __ldg(&g_u[base+ip2+j]);
    float u_jm2 = __ldg(&g_u[base+i0+jm2]);
    float u_jm1 = __ldg(&g_u[base+i0+jm1]);
    float u_jp1 = __ldg(&g_u[base+i0+jp1]);
    float u_jp2 = __ldg(&g_u[base+i0+jp2]);

    float v_im2 = __ldg(&g_v[base+im2+j]);
    float v_im1 = __ldg(&g_v[base+im1+j]);
    float v_c   = __ldg(&g_v[base+i0 +j]);
    float v_ip1 = __ldg(&g_v[base+ip1+j]);
    float v_ip2 = __ldg(&g_v[base+ip2+j]);
    float v_jm2 = __ldg(&g_v[base+i0+jm2]);
    float v_jm1 = __ldg(&g_v[base+i0+jm1]);
    float v_jp1 = __ldg(&g_v[base+i0+jp1]);
    float v_jp2 = __ldg(&g_v[base+i0+jp2]);

    float d_im2 = __ldg(&dfld[base+im2+j]);
    float d_im1 = __ldg(&dfld[base+im1+j]);
    float d_c   = __ldg(&dfld[base+i0 +j]);
    float d_ip1 = __ldg(&dfld[base+ip1+j]);
    float d_ip2 = __ldg(&dfld[base+ip2+j]);
    float d_jm2 = __ldg(&dfld[base+i0+jm2]);
    float d_jm1 = __ldg(&dfld[base+i0+jm1]);
    float d_jp1 = __ldg(&dfld[base+i0+jp1]);
    float d_jp2 = __ldg(&dfld[base+i0+jp2]);

    float uf_p = 0.5f*(u_c   + u_ip1);
    float uf_m = 0.5f*(u_im1 + u_c  );
    float vf_p = 0.5f*(v_c   + v_jp1);
    float vf_m = 0.5f*(v_jm1 + v_c  );

    {
        float Fip = face_flux(u_im1, u_c,   u_ip1, u_ip2, uf_p, dtdx);
        float Fim = face_flux(u_im2, u_im1, u_c,   u_ip1, uf_m, dtdx);
        float Fjp = face_flux(u_jm1, u_c,   u_jp1, u_jp2, vf_p, dtdx);
        float Fjm = face_flux(u_jm2, u_jm1, u_c,   u_jp1, vf_m, dtdx);
        float tend = -((Fip - Fim) + (Fjp - Fjm)) * INVDX;
        float lap  = (u_im1 + u_ip1 + u_jm1 + u_jp1 - 4.0f*u_c) * INVDX2;
        g_u1[idx] = u_c + dt*(tend + VISCF*lap);
    }
    {
        float Fip = face_flux(v_im1, v_c,   v_ip1, v_ip2, uf_p, dtdx);
        float Fim = face_flux(v_im2, v_im1, v_c,   v_ip1, uf_m, dtdx);
        float Fjp = face_flux(v_jm1, v_c,   v_jp1, v_jp2, vf_p, dtdx);
        float Fjm = face_flux(v_jm2, v_jm1, v_c,   v_jp1, vf_m, dtdx);
        float tend = -((Fip - Fim) + (Fjp - Fjm)) * INVDX;
        float lap  = (v_im1 + v_ip1 + v_jm1 + v_jp1 - 4.0f*v_c) * INVDX2;
        g_v1[idx] = v_c + dt*(tend + VISCF*lap);
    }
    {
        float Fip = face_flux(d_im1, d_c,   d_ip1, d_ip2, uf_p, dtdx);
        float Fim = face_flux(d_im2, d_im1, d_c,   d_ip1, uf_m, dtdx);
        float Fjp = face_flux(d_jm1, d_c,   d_jp1, d_jp2, vf_p, dtdx);
        float Fjm = face_flux(d_jm2, d_jm1, d_c,   d_jp1, vf_m, dtdx);
        float tend = -((Fip - Fim) + (Fjp - Fjm)) * INVDX;
        dout[idx] = d_c + dt*tend;
    }
}

// ---------------- radix-4 Stockham 256-pt FFT (64 threads per transform) ----------------
__device__ __forceinline__ float2 cmulf(float2 a, float2 b){
    return make_float2(fmaf(a.x, b.x, -a.y*b.y), fmaf(a.x, b.y, a.y*b.x));
}

template<bool INV>
__device__ __forceinline__ float2* fft256_r4(float2* sA, float2* sB, const float2* tw, int t){
    float2* src = sA; float2* dst = sB;
    #pragma unroll
    for (int st = 0; st < 4; st++){
        int s  = 1 << (2*st);
        int q  = t & (s-1);
        int sp = t - q;                    // s*p
        float2 a = src[SPAD(t)];
        float2 b = src[SPAD(t+64)];
        float2 c = src[SPAD(t+128)];
        float2 d = src[SPAD(t+192)];
        float2 w1 = tw[sp];
        if (INV) w1.y = -w1.y;
        float2 w2 = make_float2(w1.x*w1.x - w1.y*w1.y, 2.0f*w1.x*w1.y);
        float2 w3 = cmulf(w1, w2);
        float2 t0 = make_float2(a.x+c.x, a.y+c.y);
        float2 t1 = make_float2(a.x-c.x, a.y-c.y);
        float2 t2 = make_float2(b.x+d.x, b.y+d.y);
        float2 t3 = make_float2(b.x-d.x, b.y-d.y);
        float2 y0 = make_float2(t0.x+t2.x, t0.y+t2.y);
        float2 y2 = make_float2(t0.x-t2.x, t0.y-t2.y);
        float2 u1, u3;
        if (!INV){
            u1 = make_float2(t1.x + t3.y, t1.y - t3.x);   // t1 - i*t3
            u3 = make_float2(t1.x - t3.y, t1.y + t3.x);   // t1 + i*t3
        } else {
            u1 = make_float2(t1.x - t3.y, t1.y + t3.x);
            u3 = make_float2(t1.x + t3.y, t1.y - t3.x);
        }
        int o = 4*sp + q;
        dst[SPAD(o)]       = y0;
        dst[SPAD(o + s)]   = cmulf(w1, u1);
        dst[SPAD(o + 2*s)] = cmulf(w2, y2);
        dst[SPAD(o + 3*s)] = cmulf(w3, u3);
        __syncthreads();
        float2* tmp = src; src = dst; dst = tmp;
    }
    return src;   // after 4 swaps result is back in sA
}

// ---------------- K2: divergence + paired real row FFT (r2c) ----------------
// One transform per ROW PAIR: z = div(r0) + i*div(r1); untangle to half spectra.
__global__ void k_divfft(){
    __shared__ float2 sA[4][FSZ], sB[4][FSZ];
    __shared__ float2 stw[64];
    int tid = threadIdx.x;                // 256
    int f = tid >> 6, t = tid & 63;
    if (tid < 64) stw[tid] = g_tw[tid];
    int b  = blockIdx.y;
    int mp = blockIdx.x*4 + f;            // row pair 0..127
    int r0 = mp*2, r1 = r0+1;
    int base = b << 16;
    int row0 = base + (r0<<8);
    int rowm = base + (((r0-1)&255)<<8);
    int row1 = base + (r1<<8);
    #pragma unroll
    for (int m = 0; m < 4; m++){
        int j  = t + 64*m;
        int jm = (j-1)&255;
        float du0 = g_u1[row0+j] - g_u1[rowm+j];
        float dv0 = g_v1[row0+j] - g_v1[row0+jm];
        float du1 = g_u1[row1+j] - g_u1[row0+j];
        float dv1 = g_v1[row1+j] - g_v1[row1+jm];
        sA[f][SPAD(j)] = make_float2((du0+dv0)*INVDX, (du1+dv1)*INVDX);
    }
    __syncthreads();
    float2* res = fft256_r4<false>(sA[f], sB[f], stw, t);
    // untangle: R0 = (Z + conj(Zn))/2, R1 = (Z - conj(Zn))/(2i), store k=0..128
    int gb0 = (b*NG + r0)*K2P;
    int gb1 = (b*NG + r1)*K2P;
    #pragma unroll
    for (int m = 0; m < 3; m++){
        int k = t + 64*m;
        if (k <= 128){
            float2 Z  = res[SPAD(k)];
            float2 Zn = res[SPAD((256-k)&255)];
            g_G[gb0 + k] = make_float2(0.5f*(Z.x+Zn.x), 0.5f*(Z.y-Zn.y));
            g_G[gb1 + k] = make_float2(0.5f*(Z.y+Zn.y), 0.5f*(Zn.x-Z.x));
        }
    }
}

// ---------------- K3: column FFT * inv_lam * inverse column FFT (half spectrum) ----------------
__global__ void k_colsolve(){
    __shared__ float2 sA[4][FSZ], sB[4][FSZ];
    __shared__ float2 stw[64];
    int tid = threadIdx.x;                // 256
    int c = tid & 3, t = tid >> 2;        // interleaved: 4 adjacent k2 per block
    if (tid < 64) stw[tid] = g_tw[tid];
    int b  = blockIdx.y;
    int k2 = blockIdx.x*4 + c;            // 0..131 (129..131 are pad, never read back)
    int gb = b*NG*K2P + k2;
    #pragma unroll
    for (int m = 0; m < 4; m++){
        int i = t + 64*m;
        sA[c][SPAD(i)] = g_G[gb + i*K2P];
    }
    __syncthreads();
    float2* res = fft256_r4<false>(sA[c], sB[c], stw, t);
    float l2v = g_lam1[k2 & 255];
    #pragma unroll
    for (int m = 0; m < 4; m++){
        int k1 = t + 64*m;
        float sc = __fdividef(ONE65536, g_lam1[k1] + l2v);
        if ((k1 | k2) == 0) sc = 0.0f;
        float2 vz = res[SPAD(k1)];
        res[SPAD(k1)] = make_float2(vz.x*sc, vz.y*sc);
    }
    __syncthreads();
    float2* res2 = fft256_r4<true>(sA[c], sB[c], stw, t);
    #pragma unroll
    for (int m = 0; m < 4; m++){
        int i = t + 64*m;
        g_G[gb + i*K2P] = res2[SPAD(i)];
    }
}

// ---------------- K4: paired inverse row FFT (c2r) -> q ----------------
__global__ void k_rowifft(){
    __shared__ float2 sA[4][FSZ], sB[4][FSZ];
    __shared__ float2 stw[64];
    int tid = threadIdx.x;                // 256
    int f = tid >> 6, t = tid & 63;
    if (tid < 64) stw[tid] = g_tw[tid];
    int b  = blockIdx.y;
    int mp = blockIdx.x*4 + f;
    int r0 = 2*mp, r1 = r0+1;
    int gb0 = (b*NG + r0)*K2P;
    int gb1 = (b*NG + r1)*K2P;
    // assemble W[k] = Q0[k] + i*Q1[k] with hermitian extension for k>128
    #pragma unroll
    for (int m = 0; m < 4; m++){
        int k = t + 64*m;
        float2 W;
        if (k <= 128){
            float2 B0 = g_G[gb0 + k];
            float2 B1 = g_G[gb1 + k];
            W = make_float2(B0.x - B1.y, B0.y + B1.x);
        } else {
            int kp = 256 - k;             // 1..127
            float2 B0 = g_G[gb0 + kp];
            float2 B1 = g_G[gb1 + kp];
            W = make_float2(B0.x + B1.y, B1.x - B0.y);
        }
        sA[f][SPAD(k)] = W;
    }
    __syncthreads();
    float2* res = fft256_r4<true>(sA[f], sB[f], stw, t);
    int q0 = (b<<16) + (r0<<8);
    int q1 = (b<<16) + (r1<<8);
    #pragma unroll
    for (int m = 0; m < 4; m++){
        int j = t + 64*m;
        float2 z = res[SPAD(j)];
        g_q[q0 + j] = z.x;
        g_q[q1 + j] = z.y;
    }
}

// ---------------- K5: projection correction (+ optional output write) ----------------
__global__ void k_correct(float* __restrict__ out, int par_new, int tstep, int wout){
    int idx  = blockIdx.x*256 + threadIdx.x;
    int j    = idx & 255;
    int i    = (idx >> 8) & 255;
    int base = idx & ~0xFFFF;
    int i0   = i << 8;
    int ip1  = ((i + 1) & 255) << 8;
    int jp1  = (j + 1) & 255;

    float qc  = g_q[idx];
    float qip = g_q[base + ip1 + j];
    float qjp = g_q[base + i0 + jp1];

    float un = g_u1[idx] - (qip - qc) * INVDX;
    float vn = g_v1[idx] - (qjp - qc) * INVDX;
    g_u[idx] = un;
    g_v[idx] = vn;

    if (wout){
        const float* __restrict__ dnew = par_new ? g_d1 : g_d0;
        float dd = dnew[idx];
        int b  = idx >> 16;
        int ij = idx & 0xFFFF;
        size_t o = ((size_t)b * TSTEPS + (size_t)tstep) * (size_t)(NG*NG*3) + (size_t)ij * 3;
        out[o + 0] = un;
        out[o + 1] = vn;
        out[o + 2] = dd;
    }
}

// ---------------- launch ----------------
extern "C" void kernel_launch(void* const* d_in, const int* in_sizes, int n_in,
                              void* d_out, int out_size){
    const float* y0  = (const float*)d_in[0];
    const float* dtp = (const float*)d_in[1];
    float* out = (float*)d_out;

    k_tables<<<1, 256>>>();
    k_init<<<NPTS/256, 256>>>(y0);

    int par = 0;
    for (int t = 0; t < TSTEPS; t++){
        for (int k = 0; k < INNERS; k++){
            k_step<<<NPTS/256, 256>>>(dtp, par);
            k_divfft  <<<dim3(32, NB), 256>>>();
            k_colsolve<<<dim3(33, NB), 256>>>();
            k_rowifft <<<dim3(32, NB), 256>>>();
            int par_new = par ^ 1;
            k_correct<<<NPTS/256, 256>>>(out, par_new, t, (k == INNERS-1) ? 1 : 0);
            par = par_new;
        }
    }
}